// round 13
// baseline (speedup 1.0000x reference)
#include <cuda_runtime.h>

#define T_DIM 256
#define L_DIM 32
#define V_DIM 256
#define F_DIM 12
#define D_DIM 512
#define SINK_EPS 1e-6f
#define SINK_ITERS 100
#define FLT_MIN_NORMAL 1.17549435e-38f   // 2^-126

// Scratch for sims, pair-blocked: sims[(t*V+v)*384 + l*12 + f]. ~100.7 MB.
__device__ float g_sims[(size_t)T_DIM * V_DIM * L_DIM * F_DIM];

// ---------------------------------------------------------------------------
// Kernel 1: sims[t,v,l,f] = sum_d te[t,l,d] * ve[v,f,d]
// Plain fp32 SMEM-tiled NT GEMM. M=8192 (t*32+l), N=3072 (v*12+f), K=512.
// ---------------------------------------------------------------------------
#define BM 128
#define BN 128
#define BK 16

__global__ void __launch_bounds__(256) sims_gemm_kernel(
    const float* __restrict__ A,   // text_embeds  [8192, 512]
    const float* __restrict__ B)   // video_embeds [3072, 512]
{
    __shared__ float As[BK][BM];
    __shared__ float Bs[BK][BN];

    const int tid  = threadIdx.x;
    const int bm   = blockIdx.y;
    const int bn   = blockIdx.x;
    const int lrow = tid >> 2;
    const int lcol = (tid & 3) << 2;
    const int tx   = tid & 15;
    const int ty   = tid >> 4;

    const float* Ab = A + (size_t)bm * BM * D_DIM;
    const float* Bb = B + (size_t)bn * BN * D_DIM;

    float acc[8][8];
#pragma unroll
    for (int i = 0; i < 8; i++)
#pragma unroll
        for (int j = 0; j < 8; j++) acc[i][j] = 0.0f;

    for (int k0 = 0; k0 < D_DIM; k0 += BK) {
#pragma unroll
        for (int h = 0; h < 2; h++) {
            const int r = lrow + 64 * h;
            float4 va = *(const float4*)(Ab + (size_t)r * D_DIM + k0 + lcol);
            As[lcol + 0][r] = va.x;
            As[lcol + 1][r] = va.y;
            As[lcol + 2][r] = va.z;
            As[lcol + 3][r] = va.w;
            float4 vb = *(const float4*)(Bb + (size_t)r * D_DIM + k0 + lcol);
            Bs[lcol + 0][r] = vb.x;
            Bs[lcol + 1][r] = vb.y;
            Bs[lcol + 2][r] = vb.z;
            Bs[lcol + 3][r] = vb.w;
        }
        __syncthreads();

#pragma unroll
        for (int kk = 0; kk < BK; kk++) {
            float ra[8], rb[8];
            *(float4*)&ra[0] = *(const float4*)&As[kk][ty * 8];
            *(float4*)&ra[4] = *(const float4*)&As[kk][ty * 8 + 4];
            *(float4*)&rb[0] = *(const float4*)&Bs[kk][tx * 8];
            *(float4*)&rb[4] = *(const float4*)&Bs[kk][tx * 8 + 4];
#pragma unroll
            for (int i = 0; i < 8; i++)
#pragma unroll
                for (int j = 0; j < 8; j++)
                    acc[i][j] = fmaf(ra[i], rb[j], acc[i][j]);
        }
        __syncthreads();
    }

#pragma unroll
    for (int i = 0; i < 8; i++) {
        const int m  = bm * BM + ty * 8 + i;
        const int tt = m >> 5;
        const int ll = m & 31;
#pragma unroll
        for (int j = 0; j < 8; j++) {
            const int n  = bn * BN + tx * 8 + j;
            const int vv = n / 12;
            const int ff = n - vv * 12;
            g_sims[(size_t)((tt << 8) + vv) * (L_DIM * F_DIM) + ll * F_DIM + ff] =
                acc[i][j];
        }
    }
}

// ---------------------------------------------------------------------------
// XLA:GPU exp emulation: accurate expf (libdevice), output FTZ —
// results below FLT_MIN (2^-126) flush to exact 0. Handles -inf too.
// ---------------------------------------------------------------------------
__device__ __forceinline__ float ref_exp(float arg) {
    const float w = expf(arg);
    return (w < FLT_MIN_NORMAL) ? 0.0f : w;
}

// ---------------------------------------------------------------------------
// Kernel 2: LITERAL reference Sinkhorn on register-resident P[4][12].
// 8 lanes per (t,v) pair; lane g owns rows {g, g+8, g+16, g+24}.
//   P0 = w / (S + EPS)
//   loop: u_l = P.sum(-1) + EPS;  P *= r_l/u_l
//         v_f = P.sum(-2) + EPS;  P *= c_f/v_f
// P stays in normal fp32 range the whole trajectory (P0 >= w_min*1e6 ~ 1e-32,
// rises toward ~0.1): no rails, no drift, dead rows/cols/pairs exactly as ref.
// ---------------------------------------------------------------------------
__global__ void __launch_bounds__(256, 2) sinkhorn_kernel(
    const float* __restrict__ cap_mask,   // [256, 32]
    const float* __restrict__ vid_mask,   // [256, 12]
    float* __restrict__ out)              // [256, 256]
{
    const unsigned FULL = 0xffffffffu;
    const int gtid = blockIdx.x * blockDim.x + threadIdx.x;
    const int warp = gtid >> 5;
    const int lane = threadIdx.x & 31;
    const int g    = lane & 7;
    const int pair = warp * 4 + (lane >> 3);
    const int t    = pair >> 8;
    const int v    = pair & 255;

    const float4* sp = (const float4*)(g_sims + (size_t)pair * (L_DIM * F_DIM));

    // ---- masks ----
    float capv[4];
#pragma unroll
    for (int j = 0; j < 4; j++) capv[j] = cap_mask[t * L_DIM + g + 8 * j];

    float vm[12];
    {
        const float4* vmp = (const float4*)(vid_mask + v * F_DIM);
        float4 m0 = vmp[0], m1 = vmp[1], m2 = vmp[2];
        vm[0] = m0.x; vm[1] = m0.y; vm[2]  = m0.z; vm[3]  = m0.w;
        vm[4] = m1.x; vm[5] = m1.y; vm[6]  = m1.z; vm[7]  = m1.w;
        vm[8] = m2.x; vm[9] = m2.y; vm[10] = m2.z; vm[11] = m2.w;
    }

    // ---- marginals r, c ----
    float nCap = 0.0f;
#pragma unroll
    for (int j = 0; j < 4; j++) nCap += (capv[j] != 0.0f) ? 1.0f : 0.0f;
#pragma unroll
    for (int m = 1; m < 8; m <<= 1) nCap += __shfl_xor_sync(FULL, nCap, m);

    float nVid = 0.0f;
#pragma unroll
    for (int f = 0; f < 12; f++) nVid += (vm[f] != 0.0f) ? 1.0f : 0.0f;

    const bool capAny = nCap > 0.0f;
    const bool vidAny = nVid > 0.0f;

    float r[4];
#pragma unroll
    for (int j = 0; j < 4; j++)
        r[j] = (capv[j] != 0.0f && vidAny) ? (1.0f / nCap) : 0.0f;

    float c[12];
#pragma unroll
    for (int f = 0; f < 12; f++)
        c[f] = (vm[f] != 0.0f && capAny) ? (1.0f / nVid) : 0.0f;

    // ---- P = ref_exp((s-1)/0.01), masked -> 0; accumulate S ----
    // arg chain: fl(s-1), then IEEE divide by 0.01f (matches XLA lowering;
    // immune to fast-math).
    float P[4][12];
    float S = 0.0f;
#pragma unroll
    for (int j = 0; j < 4; j++) {
        const int row = g + 8 * j;
        float4 x0 = sp[row * 3 + 0];
        float4 x1 = sp[row * 3 + 1];
        float4 x2 = sp[row * 3 + 2];
        float s[12];
        s[0] = x0.x; s[1] = x0.y; s[2]  = x0.z; s[3]  = x0.w;
        s[4] = x1.x; s[5] = x1.y; s[6]  = x1.z; s[7]  = x1.w;
        s[8] = x2.x; s[9] = x2.y; s[10] = x2.z; s[11] = x2.w;
#pragma unroll
        for (int f = 0; f < 12; f++) {
            const float arg = __fdiv_rn(s[f] - 1.0f, 0.01f);
            float w = ref_exp(arg);
            w = (capv[j] != 0.0f && vm[f] != 0.0f) ? w : 0.0f;
            P[j][f] = w;
            S += w;
        }
    }
#pragma unroll
    for (int m = 1; m < 8; m <<= 1) S += __shfl_xor_sync(FULL, S, m);

    // P0 = w / (S + EPS)   (S <= ~1e-29 << EPS, so this is w * ~1e6)
    const float s0 = __fdividef(1.0f, S + SINK_EPS);
#pragma unroll
    for (int j = 0; j < 4; j++)
#pragma unroll
        for (int f = 0; f < 12; f++) P[j][f] *= s0;

    // ---- 100 literal Sinkhorn iterations ----
#pragma unroll 1
    for (int it = 0; it < SINK_ITERS; it++) {
        // row step: u = P.sum(-1) + EPS ; P *= r/u
#pragma unroll
        for (int j = 0; j < 4; j++) {
            float u = SINK_EPS;
#pragma unroll
            for (int f = 0; f < 12; f++) u += P[j][f];
            const float q = __fdividef(r[j], u);
#pragma unroll
            for (int f = 0; f < 12; f++) P[j][f] *= q;
        }
        // column step: v = P.sum(-2) + EPS ; P *= c/v
        float p[12];
#pragma unroll
        for (int f = 0; f < 12; f++)
            p[f] = (P[0][f] + P[1][f]) + (P[2][f] + P[3][f]);
#pragma unroll
        for (int m = 1; m < 8; m <<= 1)
#pragma unroll
            for (int f = 0; f < 12; f++)
                p[f] += __shfl_xor_sync(FULL, p[f], m);
#pragma unroll
        for (int f = 0; f < 12; f++) {
            const float qc = __fdividef(c[f], p[f] + SINK_EPS);
#pragma unroll
            for (int j = 0; j < 4; j++) P[j][f] *= qc;
        }
    }

    // ---- output: sum over (l,f) of sims * P ----
    float acc = 0.0f;
#pragma unroll
    for (int j = 0; j < 4; j++) {
        const int row = g + 8 * j;
        float4 x0 = sp[row * 3 + 0];
        float4 x1 = sp[row * 3 + 1];
        float4 x2 = sp[row * 3 + 2];
        float s[12];
        s[0] = x0.x; s[1] = x0.y; s[2]  = x0.z; s[3]  = x0.w;
        s[4] = x1.x; s[5] = x1.y; s[6]  = x1.z; s[7]  = x1.w;
        s[8] = x2.x; s[9] = x2.y; s[10] = x2.z; s[11] = x2.w;
#pragma unroll
        for (int f = 0; f < 12; f++) acc = fmaf(s[f], P[j][f], acc);
    }
#pragma unroll
    for (int m = 1; m < 8; m <<= 1) acc += __shfl_xor_sync(FULL, acc, m);

    if (g == 0) out[pair] = acc;
}

// ---------------------------------------------------------------------------
extern "C" void kernel_launch(void* const* d_in, const int* in_sizes, int n_in,
                              void* d_out, int out_size)
{
    // Bind inputs BY ELEMENT COUNT (all four unique) — ordering-robust.
    const float* te  = 0;   // 256*32*512  = 4194304
    const float* ve  = 0;   // 256*12*512  = 1572864
    const float* cap = 0;   // 256*32      = 8192
    const float* vid = 0;   // 256*12      = 3072
    for (int i = 0; i < n_in; i++) {
        switch (in_sizes[i]) {
            case 4194304: te  = (const float*)d_in[i]; break;
            case 1572864: ve  = (const float*)d_in[i]; break;
            case 8192:    cap = (const float*)d_in[i]; break;
            case 3072:    vid = (const float*)d_in[i]; break;
            default: break;
        }
    }
    if (!te)  te  = (const float*)d_in[0];
    if (!ve)  ve  = (const float*)d_in[1];
    if (!cap) cap = (const float*)d_in[2];
    if (!vid) vid = (const float*)d_in[3];

    float* out = (float*)d_out;                 // [256,256] float32

    dim3 gemm_grid(3072 / BN, 8192 / BM);       // (24, 64)
    sims_gemm_kernel<<<gemm_grid, 256>>>(te, ve);

    // 65536 pairs, 4 pairs/warp, 8 warps/CTA -> 2048 CTAs
    sinkhorn_kernel<<<2048, 256>>>(cap, vid, out);
}

// round 14
// speedup vs baseline: 1.6278x; 1.6278x over previous
#include <cuda_runtime.h>

#define T_DIM 256
#define L_DIM 32
#define V_DIM 256
#define F_DIM 12
#define D_DIM 512
#define SINK_EPS 1e-6f
#define SINK_ITERS 100
#define FLT_MIN_NORMAL 1.17549435e-38f   // 2^-126

// Scratch: sims, pair-blocked: sims[(t*V+v)*384 + l*12 + f]. ~100.7 MB.
__device__ float g_sims[(size_t)T_DIM * V_DIM * L_DIM * F_DIM];
// Compaction list of pairs with >=2 survivors (heavy path).
__device__ int g_count;
__device__ int g_list[T_DIM * V_DIM];

// ---------------------------------------------------------------------------
// Kernel 1: fp32 NT GEMM, double-buffered SMEM + register-staged prefetch.
// FMA order identical to the R13 passing kernel (support-critical).
// ---------------------------------------------------------------------------
#define BM 128
#define BN 128
#define BK 16

__global__ void __launch_bounds__(256, 2) sims_gemm_kernel(
    const float* __restrict__ A,   // text_embeds  [8192, 512]
    const float* __restrict__ B)   // video_embeds [3072, 512]
{
    __shared__ float As[2][BK][BM];
    __shared__ float Bs[2][BK][BN];

    if (blockIdx.x == 0 && blockIdx.y == 0 && threadIdx.x == 0) g_count = 0;

    const int tid  = threadIdx.x;
    const int bm   = blockIdx.y;
    const int bn   = blockIdx.x;
    const int lrow = tid >> 2;          // 0..63
    const int lcol = (tid & 3) << 2;    // 0,4,8,12
    const int tx   = tid & 15;
    const int ty   = tid >> 4;

    const float* Ab = A + (size_t)bm * BM * D_DIM;
    const float* Bb = B + (size_t)bn * BN * D_DIM;

    float acc[8][8];
#pragma unroll
    for (int i = 0; i < 8; i++)
#pragma unroll
        for (int j = 0; j < 8; j++) acc[i][j] = 0.0f;

    float4 va0, va1, vb0, vb1;

    // preload tile 0 into buffer 0
    va0 = *(const float4*)(Ab + (size_t)lrow * D_DIM + lcol);
    va1 = *(const float4*)(Ab + (size_t)(lrow + 64) * D_DIM + lcol);
    vb0 = *(const float4*)(Bb + (size_t)lrow * D_DIM + lcol);
    vb1 = *(const float4*)(Bb + (size_t)(lrow + 64) * D_DIM + lcol);
    As[0][lcol + 0][lrow] = va0.x; As[0][lcol + 1][lrow] = va0.y;
    As[0][lcol + 2][lrow] = va0.z; As[0][lcol + 3][lrow] = va0.w;
    As[0][lcol + 0][lrow + 64] = va1.x; As[0][lcol + 1][lrow + 64] = va1.y;
    As[0][lcol + 2][lrow + 64] = va1.z; As[0][lcol + 3][lrow + 64] = va1.w;
    Bs[0][lcol + 0][lrow] = vb0.x; Bs[0][lcol + 1][lrow] = vb0.y;
    Bs[0][lcol + 2][lrow] = vb0.z; Bs[0][lcol + 3][lrow] = vb0.w;
    Bs[0][lcol + 0][lrow + 64] = vb1.x; Bs[0][lcol + 1][lrow + 64] = vb1.y;
    Bs[0][lcol + 2][lrow + 64] = vb1.z; Bs[0][lcol + 3][lrow + 64] = vb1.w;
    __syncthreads();

    const int NT = D_DIM / BK;   // 32
    int buf = 0;
#pragma unroll 1
    for (int t = 0; t < NT; t++) {
        if (t + 1 < NT) {
            const int kn = (t + 1) * BK;
            va0 = *(const float4*)(Ab + (size_t)lrow * D_DIM + kn + lcol);
            va1 = *(const float4*)(Ab + (size_t)(lrow + 64) * D_DIM + kn + lcol);
            vb0 = *(const float4*)(Bb + (size_t)lrow * D_DIM + kn + lcol);
            vb1 = *(const float4*)(Bb + (size_t)(lrow + 64) * D_DIM + kn + lcol);
        }
#pragma unroll
        for (int kk = 0; kk < BK; kk++) {
            float ra[8], rb[8];
            *(float4*)&ra[0] = *(const float4*)&As[buf][kk][ty * 8];
            *(float4*)&ra[4] = *(const float4*)&As[buf][kk][ty * 8 + 4];
            *(float4*)&rb[0] = *(const float4*)&Bs[buf][kk][tx * 8];
            *(float4*)&rb[4] = *(const float4*)&Bs[buf][kk][tx * 8 + 4];
#pragma unroll
            for (int i = 0; i < 8; i++)
#pragma unroll
                for (int j = 0; j < 8; j++)
                    acc[i][j] = fmaf(ra[i], rb[j], acc[i][j]);
        }
        if (t + 1 < NT) {
            const int nb = buf ^ 1;
            // safe: nobody has read buffer nb since the last __syncthreads()
            As[nb][lcol + 0][lrow] = va0.x; As[nb][lcol + 1][lrow] = va0.y;
            As[nb][lcol + 2][lrow] = va0.z; As[nb][lcol + 3][lrow] = va0.w;
            As[nb][lcol + 0][lrow + 64] = va1.x; As[nb][lcol + 1][lrow + 64] = va1.y;
            As[nb][lcol + 2][lrow + 64] = va1.z; As[nb][lcol + 3][lrow + 64] = va1.w;
            Bs[nb][lcol + 0][lrow] = vb0.x; Bs[nb][lcol + 1][lrow] = vb0.y;
            Bs[nb][lcol + 2][lrow] = vb0.z; Bs[nb][lcol + 3][lrow] = vb0.w;
            Bs[nb][lcol + 0][lrow + 64] = vb1.x; Bs[nb][lcol + 1][lrow + 64] = vb1.y;
            Bs[nb][lcol + 2][lrow + 64] = vb1.z; Bs[nb][lcol + 3][lrow + 64] = vb1.w;
            __syncthreads();
            buf = nb;
        }
    }

#pragma unroll
    for (int i = 0; i < 8; i++) {
        const int m  = bm * BM + ty * 8 + i;
        const int tt = m >> 5;
        const int ll = m & 31;
#pragma unroll
        for (int j = 0; j < 8; j++) {
            const int n  = bn * BN + tx * 8 + j;
            const int vv = n / 12;
            const int ff = n - vv * 12;
            g_sims[(size_t)((tt << 8) + vv) * (L_DIM * F_DIM) + ll * F_DIM + ff] =
                acc[i][j];
        }
    }
}

// XLA:GPU exp: accurate expf, output FTZ (results < FLT_MIN -> exact 0).
__device__ __forceinline__ float ref_exp(float arg) {
    const float w = expf(arg);
    return (w < FLT_MIN_NORMAL) ? 0.0f : w;
}

// ---------------------------------------------------------------------------
// Kernel 2a (prep): per pair, count survivors k.
//   k==0: out = 0.   k==1: 100-step scalar recurrence (fp32-op-identical to
//   the dense loop, since zeros are additive identities).   k>=2: append pair
//   to g_list (warp-aggregated atomic).
// 8 lanes per pair; lane g owns rows {g, g+8, g+16, g+24}.
// ---------------------------------------------------------------------------
__global__ void __launch_bounds__(256) sinkhorn_prep_kernel(
    const float* __restrict__ cap_mask,   // [256, 32]
    const float* __restrict__ vid_mask,   // [256, 12]
    float* __restrict__ out)              // [256, 256]
{
    const unsigned FULL = 0xffffffffu;
    const int gtid = blockIdx.x * blockDim.x + threadIdx.x;
    const int warp = gtid >> 5;
    const int lane = threadIdx.x & 31;
    const int g    = lane & 7;
    const int pair = warp * 4 + (lane >> 3);
    const int t    = pair >> 8;
    const int v    = pair & 255;

    const float4* sp = (const float4*)(g_sims + (size_t)pair * (L_DIM * F_DIM));

    // masks
    float capv[4];
#pragma unroll
    for (int j = 0; j < 4; j++) capv[j] = cap_mask[t * L_DIM + g + 8 * j];
    float vm[12];
    {
        const float4* vmp = (const float4*)(vid_mask + v * F_DIM);
        float4 m0 = vmp[0], m1 = vmp[1], m2 = vmp[2];
        vm[0] = m0.x; vm[1] = m0.y; vm[2]  = m0.z; vm[3]  = m0.w;
        vm[4] = m1.x; vm[5] = m1.y; vm[6]  = m1.z; vm[7]  = m1.w;
        vm[8] = m2.x; vm[9] = m2.y; vm[10] = m2.z; vm[11] = m2.w;
    }

    // marginals
    float nCap = 0.0f;
#pragma unroll
    for (int j = 0; j < 4; j++) nCap += (capv[j] != 0.0f) ? 1.0f : 0.0f;
#pragma unroll
    for (int m = 1; m < 8; m <<= 1) nCap += __shfl_xor_sync(FULL, nCap, m);
    float nVid = 0.0f;
#pragma unroll
    for (int f = 0; f < 12; f++) nVid += (vm[f] != 0.0f) ? 1.0f : 0.0f;
    const bool capAny = nCap > 0.0f;
    const bool vidAny = nVid > 0.0f;

    // survivor scan: count per lane; capture the (unique-if-cnt==1) survivor
    int   cnt = 0;
    float w1 = 0.0f, r1 = 0.0f, c1 = 0.0f, s1 = 0.0f;
#pragma unroll
    for (int j = 0; j < 4; j++) {
        const int row = g + 8 * j;
        const float rj = (capv[j] != 0.0f && vidAny) ? (1.0f / nCap) : 0.0f;
        float4 x0 = sp[row * 3 + 0];
        float4 x1 = sp[row * 3 + 1];
        float4 x2 = sp[row * 3 + 2];
        float s[12];
        s[0] = x0.x; s[1] = x0.y; s[2]  = x0.z; s[3]  = x0.w;
        s[4] = x1.x; s[5] = x1.y; s[6]  = x1.z; s[7]  = x1.w;
        s[8] = x2.x; s[9] = x2.y; s[10] = x2.z; s[11] = x2.w;
#pragma unroll
        for (int f = 0; f < 12; f++) {
            const float arg = __fdiv_rn(s[f] - 1.0f, 0.01f);
            float w = ref_exp(arg);
            w = (capv[j] != 0.0f && vm[f] != 0.0f) ? w : 0.0f;
            if (w != 0.0f) {
                cnt++;
                w1 = w;
                r1 = rj;
                c1 = (vm[f] != 0.0f && capAny) ? (1.0f / nVid) : 0.0f;
                s1 = s[f];
            }
        }
    }
    int k = cnt;
#pragma unroll
    for (int m = 1; m < 8; m <<= 1) k += __shfl_xor_sync(FULL, k, m);

    if (k == 0) {
        if (g == 0) out[pair] = 0.0f;
    } else if (k == 1) {
        // scalar literal Sinkhorn on the single survivor (runs on all lanes
        // in lockstep; dead lanes carry x = 0 harmlessly)
        float x = w1 * __fdividef(1.0f, w1 + SINK_EPS);   // P0 = w/(S+EPS), S=w1
#pragma unroll 1
        for (int it = 0; it < SINK_ITERS; it++) {
            const float u = SINK_EPS + x;
            x *= __fdividef(r1, u);                       // row step
            x *= __fdividef(c1, x + SINK_EPS);            // col step
        }
        if (cnt == 1) out[pair] = fmaf(s1, x, 0.0f);
    }

    // k >= 2: warp-aggregated append to heavy list
    const bool isLive = (k >= 2) && (g == 0);
    const unsigned bal = __ballot_sync(FULL, isLive);
    if (bal) {
        const int leader = __ffs(bal) - 1;
        int base = 0;
        if (lane == leader) base = atomicAdd(&g_count, __popc(bal));
        base = __shfl_sync(FULL, base, leader);
        if (isLive)
            g_list[base + __popc(bal & ((1u << lane) - 1))] = pair;
    }
}

// ---------------------------------------------------------------------------
// Kernel 2b (heavy): literal dense Sinkhorn (unchanged R13 code path) over
// the compacted k>=2 list only. Fixed grid; idle warps exit; clamped
// duplicates recompute identical values (deterministic).
// ---------------------------------------------------------------------------
__global__ void __launch_bounds__(256, 2) sinkhorn_heavy_kernel(
    const float* __restrict__ cap_mask,
    const float* __restrict__ vid_mask,
    float* __restrict__ out)
{
    const unsigned FULL = 0xffffffffu;
    const int gtid = blockIdx.x * blockDim.x + threadIdx.x;
    const int warp = gtid >> 5;
    const int lane = threadIdx.x & 31;
    const int g    = lane & 7;

    const int count = g_count;
    if (warp * 4 >= count) return;
    int lidx = warp * 4 + (lane >> 3);
    if (lidx >= count) lidx = count - 1;     // duplicate-benign
    const int pair = g_list[lidx];
    const int t    = pair >> 8;
    const int v    = pair & 255;

    const float4* sp = (const float4*)(g_sims + (size_t)pair * (L_DIM * F_DIM));

    float capv[4];
#pragma unroll
    for (int j = 0; j < 4; j++) capv[j] = cap_mask[t * L_DIM + g + 8 * j];
    float vm[12];
    {
        const float4* vmp = (const float4*)(vid_mask + v * F_DIM);
        float4 m0 = vmp[0], m1 = vmp[1], m2 = vmp[2];
        vm[0] = m0.x; vm[1] = m0.y; vm[2]  = m0.z; vm[3]  = m0.w;
        vm[4] = m1.x; vm[5] = m1.y; vm[6]  = m1.z; vm[7]  = m1.w;
        vm[8] = m2.x; vm[9] = m2.y; vm[10] = m2.z; vm[11] = m2.w;
    }

    float nCap = 0.0f;
#pragma unroll
    for (int j = 0; j < 4; j++) nCap += (capv[j] != 0.0f) ? 1.0f : 0.0f;
#pragma unroll
    for (int m = 1; m < 8; m <<= 1) nCap += __shfl_xor_sync(FULL, nCap, m);
    float nVid = 0.0f;
#pragma unroll
    for (int f = 0; f < 12; f++) nVid += (vm[f] != 0.0f) ? 1.0f : 0.0f;
    const bool capAny = nCap > 0.0f;
    const bool vidAny = nVid > 0.0f;

    float r[4];
#pragma unroll
    for (int j = 0; j < 4; j++)
        r[j] = (capv[j] != 0.0f && vidAny) ? (1.0f / nCap) : 0.0f;
    float c[12];
#pragma unroll
    for (int f = 0; f < 12; f++)
        c[f] = (vm[f] != 0.0f && capAny) ? (1.0f / nVid) : 0.0f;

    float P[4][12];
    float S = 0.0f;
#pragma unroll
    for (int j = 0; j < 4; j++) {
        const int row = g + 8 * j;
        float4 x0 = sp[row * 3 + 0];
        float4 x1 = sp[row * 3 + 1];
        float4 x2 = sp[row * 3 + 2];
        float s[12];
        s[0] = x0.x; s[1] = x0.y; s[2]  = x0.z; s[3]  = x0.w;
        s[4] = x1.x; s[5] = x1.y; s[6]  = x1.z; s[7]  = x1.w;
        s[8] = x2.x; s[9] = x2.y; s[10] = x2.z; s[11] = x2.w;
#pragma unroll
        for (int f = 0; f < 12; f++) {
            const float arg = __fdiv_rn(s[f] - 1.0f, 0.01f);
            float w = ref_exp(arg);
            w = (capv[j] != 0.0f && vm[f] != 0.0f) ? w : 0.0f;
            P[j][f] = w;
            S += w;
        }
    }
#pragma unroll
    for (int m = 1; m < 8; m <<= 1) S += __shfl_xor_sync(FULL, S, m);

    const float s0 = __fdividef(1.0f, S + SINK_EPS);
#pragma unroll
    for (int j = 0; j < 4; j++)
#pragma unroll
        for (int f = 0; f < 12; f++) P[j][f] *= s0;

#pragma unroll 1
    for (int it = 0; it < SINK_ITERS; it++) {
#pragma unroll
        for (int j = 0; j < 4; j++) {
            float u = SINK_EPS;
#pragma unroll
            for (int f = 0; f < 12; f++) u += P[j][f];
            const float q = __fdividef(r[j], u);
#pragma unroll
            for (int f = 0; f < 12; f++) P[j][f] *= q;
        }
        float p[12];
#pragma unroll
        for (int f = 0; f < 12; f++)
            p[f] = (P[0][f] + P[1][f]) + (P[2][f] + P[3][f]);
#pragma unroll
        for (int m = 1; m < 8; m <<= 1)
#pragma unroll
            for (int f = 0; f < 12; f++)
                p[f] += __shfl_xor_sync(FULL, p[f], m);
#pragma unroll
        for (int f = 0; f < 12; f++) {
            const float qc = __fdividef(c[f], p[f] + SINK_EPS);
#pragma unroll
            for (int j = 0; j < 4; j++) P[j][f] *= qc;
        }
    }

    float acc = 0.0f;
#pragma unroll
    for (int j = 0; j < 4; j++) {
        const int row = g + 8 * j;
        float4 x0 = sp[row * 3 + 0];
        float4 x1 = sp[row * 3 + 1];
        float4 x2 = sp[row * 3 + 2];
        float s[12];
        s[0] = x0.x; s[1] = x0.y; s[2]  = x0.z; s[3]  = x0.w;
        s[4] = x1.x; s[5] = x1.y; s[6]  = x1.z; s[7]  = x1.w;
        s[8] = x2.x; s[9] = x2.y; s[10] = x2.z; s[11] = x2.w;
#pragma unroll
        for (int f = 0; f < 12; f++) acc = fmaf(s[f], P[j][f], acc);
    }
#pragma unroll
    for (int m = 1; m < 8; m <<= 1) acc += __shfl_xor_sync(FULL, acc, m);

    if (g == 0) out[pair] = acc;
}

// ---------------------------------------------------------------------------
extern "C" void kernel_launch(void* const* d_in, const int* in_sizes, int n_in,
                              void* d_out, int out_size)
{
    const float* te  = 0;   // 4194304
    const float* ve  = 0;   // 1572864
    const float* cap = 0;   // 8192
    const float* vid = 0;   // 3072
    for (int i = 0; i < n_in; i++) {
        switch (in_sizes[i]) {
            case 4194304: te  = (const float*)d_in[i]; break;
            case 1572864: ve  = (const float*)d_in[i]; break;
            case 8192:    cap = (const float*)d_in[i]; break;
            case 3072:    vid = (const float*)d_in[i]; break;
            default: break;
        }
    }
    if (!te)  te  = (const float*)d_in[0];
    if (!ve)  ve  = (const float*)d_in[1];
    if (!cap) cap = (const float*)d_in[2];
    if (!vid) vid = (const float*)d_in[3];

    float* out = (float*)d_out;                 // [256,256] float32

    dim3 gemm_grid(3072 / BN, 8192 / BM);       // (24, 64); also zeroes g_count
    sims_gemm_kernel<<<gemm_grid, 256>>>(te, ve);

    sinkhorn_prep_kernel<<<2048, 256>>>(cap, vid, out);
    sinkhorn_heavy_kernel<<<2048, 256>>>(cap, vid, out);
}

// round 15
// speedup vs baseline: 1.8288x; 1.1235x over previous
#include <cuda_runtime.h>

#define T_DIM 256
#define L_DIM 32
#define V_DIM 256
#define F_DIM 12
#define D_DIM 512
#define SINK_EPS 1e-6f
#define SINK_ITERS 100
#define FLT_MIN_NORMAL 1.17549435e-38f   // 2^-126
// s below this can never survive FTZ flush: arg=(s-1)/0.01 < -87.35 < ln(FLT_MIN)
#define S_SKIP 0.1265f

// Scratch: sims, pair-blocked: sims[(t*V+v)*384 + l*12 + f]. ~100.7 MB.
__device__ float g_sims[(size_t)T_DIM * V_DIM * L_DIM * F_DIM];
// Compaction list of pairs with >=2 survivors (heavy path).
__device__ int g_count;
__device__ int g_list[T_DIM * V_DIM];

// ---------------------------------------------------------------------------
// Kernel 1: fp32 NT GEMM, double-buffered, XOR-swizzled SMEM (conflict-free
// loads AND stores). Per-output FMA k-order identical to R13/R14 (bit-exact).
// ---------------------------------------------------------------------------
#define BM 128
#define BN 128
#define BK 16

// logical index x in a BK-row kk stored at physical x ^ (((kk>>2)&3)<<3)
#define SWZ(kk) ((((kk) >> 2) & 3) << 3)

__global__ void __launch_bounds__(256, 2) sims_gemm_kernel(
    const float* __restrict__ A,   // text_embeds  [8192, 512]
    const float* __restrict__ B)   // video_embeds [3072, 512]
{
    __shared__ float As[2][BK][BM];
    __shared__ float Bs[2][BK][BN];

    if (blockIdx.x == 0 && blockIdx.y == 0 && threadIdx.x == 0) g_count = 0;

    const int tid  = threadIdx.x;
    const int bm   = blockIdx.y;
    const int bn   = blockIdx.x;
    const int lrow = tid >> 2;          // 0..63
    const int lcol = (tid & 3) << 2;    // 0,4,8,12
    const int swz  = (tid & 3) << 3;    // == SWZ(lcol+i) for i in 0..3
    const int tx   = tid & 15;
    const int ty   = tid >> 4;

    const float* Ab = A + (size_t)bm * BM * D_DIM;
    const float* Bb = B + (size_t)bn * BN * D_DIM;

    float acc[8][8];
#pragma unroll
    for (int i = 0; i < 8; i++)
#pragma unroll
        for (int j = 0; j < 8; j++) acc[i][j] = 0.0f;

    float4 va0, va1, vb0, vb1;

    // preload tile 0 into buffer 0 (swizzled stores: conflict-free)
    va0 = *(const float4*)(Ab + (size_t)lrow * D_DIM + lcol);
    va1 = *(const float4*)(Ab + (size_t)(lrow + 64) * D_DIM + lcol);
    vb0 = *(const float4*)(Bb + (size_t)lrow * D_DIM + lcol);
    vb1 = *(const float4*)(Bb + (size_t)(lrow + 64) * D_DIM + lcol);
    {
        const int r0 = lrow ^ swz, r1 = (lrow + 64) ^ swz;
        As[0][lcol + 0][r0] = va0.x; As[0][lcol + 1][r0] = va0.y;
        As[0][lcol + 2][r0] = va0.z; As[0][lcol + 3][r0] = va0.w;
        As[0][lcol + 0][r1] = va1.x; As[0][lcol + 1][r1] = va1.y;
        As[0][lcol + 2][r1] = va1.z; As[0][lcol + 3][r1] = va1.w;
        Bs[0][lcol + 0][r0] = vb0.x; Bs[0][lcol + 1][r0] = vb0.y;
        Bs[0][lcol + 2][r0] = vb0.z; Bs[0][lcol + 3][r0] = vb0.w;
        Bs[0][lcol + 0][r1] = vb1.x; Bs[0][lcol + 1][r1] = vb1.y;
        Bs[0][lcol + 2][r1] = vb1.z; Bs[0][lcol + 3][r1] = vb1.w;
    }
    __syncthreads();

    const int NT = D_DIM / BK;   // 32
    int buf = 0;
#pragma unroll 1
    for (int t = 0; t < NT; t++) {
        if (t + 1 < NT) {
            const int kn = (t + 1) * BK;
            va0 = *(const float4*)(Ab + (size_t)lrow * D_DIM + kn + lcol);
            va1 = *(const float4*)(Ab + (size_t)(lrow + 64) * D_DIM + kn + lcol);
            vb0 = *(const float4*)(Bb + (size_t)lrow * D_DIM + kn + lcol);
            vb1 = *(const float4*)(Bb + (size_t)(lrow + 64) * D_DIM + kn + lcol);
        }
#pragma unroll
        for (int kk = 0; kk < BK; kk++) {
            const int sw = SWZ(kk);
            float ra[8], rb[8];
            // A: half-warp broadcast reads, conflict-free
            const int a0 = (ty * 8) ^ sw;
            *(float4*)&ra[0] = *(const float4*)&As[buf][kk][a0];
            *(float4*)&ra[4] = *(const float4*)&As[buf][kk][a0 + 4];
            // B: split-chunk mapping (tx*4 and 64+tx*4): phase-contiguous,
            // conflict-free under the swizzle
            const int b0 = (tx * 4) ^ sw;
            *(float4*)&rb[0] = *(const float4*)&Bs[buf][kk][b0];
            *(float4*)&rb[4] = *(const float4*)&Bs[buf][kk][b0 + 64];
#pragma unroll
            for (int i = 0; i < 8; i++)
#pragma unroll
                for (int j = 0; j < 8; j++)
                    acc[i][j] = fmaf(ra[i], rb[j], acc[i][j]);
        }
        if (t + 1 < NT) {
            const int nb = buf ^ 1;
            const int r0 = lrow ^ swz, r1 = (lrow + 64) ^ swz;
            As[nb][lcol + 0][r0] = va0.x; As[nb][lcol + 1][r0] = va0.y;
            As[nb][lcol + 2][r0] = va0.z; As[nb][lcol + 3][r0] = va0.w;
            As[nb][lcol + 0][r1] = va1.x; As[nb][lcol + 1][r1] = va1.y;
            As[nb][lcol + 2][r1] = va1.z; As[nb][lcol + 3][r1] = va1.w;
            Bs[nb][lcol + 0][r0] = vb0.x; Bs[nb][lcol + 1][r0] = vb0.y;
            Bs[nb][lcol + 2][r0] = vb0.z; Bs[nb][lcol + 3][r0] = vb0.w;
            Bs[nb][lcol + 0][r1] = vb1.x; Bs[nb][lcol + 1][r1] = vb1.y;
            Bs[nb][lcol + 2][r1] = vb1.z; Bs[nb][lcol + 3][r1] = vb1.w;
            __syncthreads();
            buf = nb;
        }
    }

    // Epilogue. Column mapping matches the split-chunk register layout:
    // j<4 -> n = tx*4+j ; j>=4 -> n = 64 + tx*4 + (j-4).
#pragma unroll
    for (int i = 0; i < 8; i++) {
        const int m  = bm * BM + ty * 8 + i;
        const int tt = m >> 5;
        const int ll = m & 31;
#pragma unroll
        for (int j = 0; j < 8; j++) {
            const int nl = (j < 4) ? (tx * 4 + j) : (64 + tx * 4 + (j - 4));
            const int n  = bn * BN + nl;
            const int vv = n / 12;
            const int ff = n - vv * 12;
            g_sims[(size_t)((tt << 8) + vv) * (L_DIM * F_DIM) + ll * F_DIM + ff] =
                acc[i][j];
        }
    }
}

// XLA:GPU exp: accurate expf, output FTZ (results < FLT_MIN -> exact 0).
__device__ __forceinline__ float ref_exp(float arg) {
    const float w = expf(arg);
    return (w < FLT_MIN_NORMAL) ? 0.0f : w;
}

// w for entry s (masked handled by caller). Skips expf when provably flushed.
__device__ __forceinline__ float entry_w(float s) {
    if (s <= S_SKIP) return 0.0f;             // always flushed: exact
    return ref_exp(__fdiv_rn(s - 1.0f, 0.01f));
}

// ---------------------------------------------------------------------------
// Kernel 2a (prep): classify pairs. k==0 -> 0. k==1 -> scalar recurrence with
// exact period-2 cycle shortcut. k>=2 -> compact list.
// ---------------------------------------------------------------------------
__global__ void __launch_bounds__(256) sinkhorn_prep_kernel(
    const float* __restrict__ cap_mask,   // [256, 32]
    const float* __restrict__ vid_mask,   // [256, 12]
    float* __restrict__ out)              // [256, 256]
{
    const unsigned FULL = 0xffffffffu;
    const int gtid = blockIdx.x * blockDim.x + threadIdx.x;
    const int warp = gtid >> 5;
    const int lane = threadIdx.x & 31;
    const int g    = lane & 7;
    const int pair = warp * 4 + (lane >> 3);
    const int t    = pair >> 8;
    const int v    = pair & 255;

    const float4* sp = (const float4*)(g_sims + (size_t)pair * (L_DIM * F_DIM));

    float capv[4];
#pragma unroll
    for (int j = 0; j < 4; j++) capv[j] = cap_mask[t * L_DIM + g + 8 * j];
    float vm[12];
    {
        const float4* vmp = (const float4*)(vid_mask + v * F_DIM);
        float4 m0 = vmp[0], m1 = vmp[1], m2 = vmp[2];
        vm[0] = m0.x; vm[1] = m0.y; vm[2]  = m0.z; vm[3]  = m0.w;
        vm[4] = m1.x; vm[5] = m1.y; vm[6]  = m1.z; vm[7]  = m1.w;
        vm[8] = m2.x; vm[9] = m2.y; vm[10] = m2.z; vm[11] = m2.w;
    }

    float nCap = 0.0f;
#pragma unroll
    for (int j = 0; j < 4; j++) nCap += (capv[j] != 0.0f) ? 1.0f : 0.0f;
#pragma unroll
    for (int m = 1; m < 8; m <<= 1) nCap += __shfl_xor_sync(FULL, nCap, m);
    float nVid = 0.0f;
#pragma unroll
    for (int f = 0; f < 12; f++) nVid += (vm[f] != 0.0f) ? 1.0f : 0.0f;
    const bool capAny = nCap > 0.0f;
    const bool vidAny = nVid > 0.0f;

    int   cnt = 0;
    float w1 = 0.0f, r1 = 0.0f, c1 = 0.0f, s1 = 0.0f;
#pragma unroll
    for (int j = 0; j < 4; j++) {
        const int row = g + 8 * j;
        const float rj = (capv[j] != 0.0f && vidAny) ? (1.0f / nCap) : 0.0f;
        float4 x0 = sp[row * 3 + 0];
        float4 x1 = sp[row * 3 + 1];
        float4 x2 = sp[row * 3 + 2];
        float s[12];
        s[0] = x0.x; s[1] = x0.y; s[2]  = x0.z; s[3]  = x0.w;
        s[4] = x1.x; s[5] = x1.y; s[6]  = x1.z; s[7]  = x1.w;
        s[8] = x2.x; s[9] = x2.y; s[10] = x2.z; s[11] = x2.w;
#pragma unroll
        for (int f = 0; f < 12; f++) {
            float w = entry_w(s[f]);
            w = (capv[j] != 0.0f && vm[f] != 0.0f) ? w : 0.0f;
            if (w != 0.0f) {
                cnt++;
                w1 = w;
                r1 = rj;
                c1 = (vm[f] != 0.0f && capAny) ? (1.0f / nVid) : 0.0f;
                s1 = s[f];
            }
        }
    }
    int k = cnt;
#pragma unroll
    for (int m = 1; m < 8; m <<= 1) k += __shfl_xor_sync(FULL, k, m);

    if (k == 0) {
        if (g == 0) out[pair] = 0.0f;
    } else if (k == 1) {
        // x_0 = w/(S+EPS); iterate f = (col step)∘(row step); exact period-2
        // shortcut: if x_i == x_{i-2}, the tail is periodic; pick by parity.
        float xa = w1 * __fdividef(1.0f, w1 + SINK_EPS);   // x_0
        float xb;
        {
            float tmp = xa * __fdividef(r1, SINK_EPS + xa);
            xb = tmp * __fdividef(c1, tmp + SINK_EPS);     // x_1
        }
        float xf = xb;
#pragma unroll 1
        for (int i = 2; i <= SINK_ITERS; i++) {
            float tmp = xb * __fdividef(r1, SINK_EPS + xb);
            float xc = tmp * __fdividef(c1, tmp + SINK_EPS);   // x_i
            if (__float_as_uint(xc) == __float_as_uint(xa)) {
                xf = (((SINK_ITERS - i) & 1) == 0) ? xc : xb;
                break;
            }
            xa = xb; xb = xc; xf = xc;
        }
        if (cnt == 1) out[pair] = fmaf(s1, xf, 0.0f);
    }

    const bool isLive = (k >= 2) && (g == 0);
    const unsigned bal = __ballot_sync(FULL, isLive);
    if (bal) {
        const int leader = __ffs(bal) - 1;
        int base = 0;
        if (lane == leader) base = atomicAdd(&g_count, __popc(bal));
        base = __shfl_sync(FULL, base, leader);
        if (isLive)
            g_list[base + __popc(bal & ((1u << lane) - 1))] = pair;
    }
}

// ---------------------------------------------------------------------------
// Kernel 2b (heavy): literal dense Sinkhorn over the k>=2 list (bit-exact
// R13 arithmetic). Idle warps exit; duplicates benign.
// ---------------------------------------------------------------------------
__global__ void __launch_bounds__(256, 2) sinkhorn_heavy_kernel(
    const float* __restrict__ cap_mask,
    const float* __restrict__ vid_mask,
    float* __restrict__ out)
{
    const unsigned FULL = 0xffffffffu;
    const int gtid = blockIdx.x * blockDim.x + threadIdx.x;
    const int warp = gtid >> 5;
    const int lane = threadIdx.x & 31;
    const int g    = lane & 7;

    const int count = g_count;
    if (warp * 4 >= count) return;
    int lidx = warp * 4 + (lane >> 3);
    if (lidx >= count) lidx = count - 1;
    const int pair = g_list[lidx];
    const int t    = pair >> 8;
    const int v    = pair & 255;

    const float4* sp = (const float4*)(g_sims + (size_t)pair * (L_DIM * F_DIM));

    float capv[4];
#pragma unroll
    for (int j = 0; j < 4; j++) capv[j] = cap_mask[t * L_DIM + g + 8 * j];
    float vm[12];
    {
        const float4* vmp = (const float4*)(vid_mask + v * F_DIM);
        float4 m0 = vmp[0], m1 = vmp[1], m2 = vmp[2];
        vm[0] = m0.x; vm[1] = m0.y; vm[2]  = m0.z; vm[3]  = m0.w;
        vm[4] = m1.x; vm[5] = m1.y; vm[6]  = m1.z; vm[7]  = m1.w;
        vm[8] = m2.x; vm[9] = m2.y; vm[10] = m2.z; vm[11] = m2.w;
    }

    float nCap = 0.0f;
#pragma unroll
    for (int j = 0; j < 4; j++) nCap += (capv[j] != 0.0f) ? 1.0f : 0.0f;
#pragma unroll
    for (int m = 1; m < 8; m <<= 1) nCap += __shfl_xor_sync(FULL, nCap, m);
    float nVid = 0.0f;
#pragma unroll
    for (int f = 0; f < 12; f++) nVid += (vm[f] != 0.0f) ? 1.0f : 0.0f;
    const bool capAny = nCap > 0.0f;
    const bool vidAny = nVid > 0.0f;

    float r[4];
#pragma unroll
    for (int j = 0; j < 4; j++)
        r[j] = (capv[j] != 0.0f && vidAny) ? (1.0f / nCap) : 0.0f;
    float c[12];
#pragma unroll
    for (int f = 0; f < 12; f++)
        c[f] = (vm[f] != 0.0f && capAny) ? (1.0f / nVid) : 0.0f;

    float P[4][12];
    float S = 0.0f;
#pragma unroll
    for (int j = 0; j < 4; j++) {
        const int row = g + 8 * j;
        float4 x0 = sp[row * 3 + 0];
        float4 x1 = sp[row * 3 + 1];
        float4 x2 = sp[row * 3 + 2];
        float s[12];
        s[0] = x0.x; s[1] = x0.y; s[2]  = x0.z; s[3]  = x0.w;
        s[4] = x1.x; s[5] = x1.y; s[6]  = x1.z; s[7]  = x1.w;
        s[8] = x2.x; s[9] = x2.y; s[10] = x2.z; s[11] = x2.w;
#pragma unroll
        for (int f = 0; f < 12; f++) {
            float w = entry_w(s[f]);
            w = (capv[j] != 0.0f && vm[f] != 0.0f) ? w : 0.0f;
            P[j][f] = w;
            S += w;
        }
    }
#pragma unroll
    for (int m = 1; m < 8; m <<= 1) S += __shfl_xor_sync(FULL, S, m);

    const float s0 = __fdividef(1.0f, S + SINK_EPS);
#pragma unroll
    for (int j = 0; j < 4; j++)
#pragma unroll
        for (int f = 0; f < 12; f++) P[j][f] *= s0;

#pragma unroll 1
    for (int it = 0; it < SINK_ITERS; it++) {
#pragma unroll
        for (int j = 0; j < 4; j++) {
            float u = SINK_EPS;
#pragma unroll
            for (int f = 0; f < 12; f++) u += P[j][f];
            const float q = __fdividef(r[j], u);
#pragma unroll
            for (int f = 0; f < 12; f++) P[j][f] *= q;
        }
        float p[12];
#pragma unroll
        for (int f = 0; f < 12; f++)
            p[f] = (P[0][f] + P[1][f]) + (P[2][f] + P[3][f]);
#pragma unroll
        for (int m = 1; m < 8; m <<= 1)
#pragma unroll
            for (int f = 0; f < 12; f++)
                p[f] += __shfl_xor_sync(FULL, p[f], m);
#pragma unroll
        for (int f = 0; f < 12; f++) {
            const float qc = __fdividef(c[f], p[f] + SINK_EPS);
#pragma unroll
            for (int j = 0; j < 4; j++) P[j][f] *= qc;
        }
    }

    float acc = 0.0f;
#pragma unroll
    for (int j = 0; j < 4; j++) {
        const int row = g + 8 * j;
        float4 x0 = sp[row * 3 + 0];
        float4 x1 = sp[row * 3 + 1];
        float4 x2 = sp[row * 3 + 2];
        float s[12];
        s[0] = x0.x; s[1] = x0.y; s[2]  = x0.z; s[3]  = x0.w;
        s[4] = x1.x; s[5] = x1.y; s[6]  = x1.z; s[7]  = x1.w;
        s[8] = x2.x; s[9] = x2.y; s[10] = x2.z; s[11] = x2.w;
#pragma unroll
        for (int f = 0; f < 12; f++) acc = fmaf(s[f], P[j][f], acc);
    }
#pragma unroll
    for (int m = 1; m < 8; m <<= 1) acc += __shfl_xor_sync(FULL, acc, m);

    if (g == 0) out[pair] = acc;
}

// ---------------------------------------------------------------------------
extern "C" void kernel_launch(void* const* d_in, const int* in_sizes, int n_in,
                              void* d_out, int out_size)
{
    const float* te  = 0;   // 4194304
    const float* ve  = 0;   // 1572864
    const float* cap = 0;   // 8192
    const float* vid = 0;   // 3072
    for (int i = 0; i < n_in; i++) {
        switch (in_sizes[i]) {
            case 4194304: te  = (const float*)d_in[i]; break;
            case 1572864: ve  = (const float*)d_in[i]; break;
            case 8192:    cap = (const float*)d_in[i]; break;
            case 3072:    vid = (const float*)d_in[i]; break;
            default: break;
        }
    }
    if (!te)  te  = (const float*)d_in[0];
    if (!ve)  ve  = (const float*)d_in[1];
    if (!cap) cap = (const float*)d_in[2];
    if (!vid) vid = (const float*)d_in[3];

    float* out = (float*)d_out;                 // [256,256] float32

    dim3 gemm_grid(3072 / BN, 8192 / BM);       // (24, 64); also zeroes g_count
    sims_gemm_kernel<<<gemm_grid, 256>>>(te, ve);

    sinkhorn_prep_kernel<<<2048, 256>>>(cap, vid, out);
    sinkhorn_heavy_kernel<<<2048, 256>>>(cap, vid, out);
}

// round 16
// speedup vs baseline: 2.7300x; 1.4928x over previous
#include <cuda_runtime.h>

#define T_DIM 256
#define L_DIM 32
#define V_DIM 256
#define F_DIM 12
#define D_DIM 512
#define SINK_EPS 1e-6f
#define SINK_ITERS 100
#define FLT_MIN_NORMAL 1.17549435e-38f   // 2^-126
// s below this can never survive FTZ flush: arg=(s-1)/0.01 < -87.35 < ln(FLT_MIN)
#define S_SKIP 0.1265f
// TF32-screen flag threshold: |tf32_gemm - exact| <= 2^-11*||a||*||b|| + accum ~ 7e-4.
// Any exact survivor (s >= 0.126635) has approx >= 0.1259 >> 0.124. Sound.
#define FLAG_THR 0.124f

// Scratch: sims, pair-blocked: sims[(t*V+v)*384 + l*12 + f]. ~100.7 MB.
__device__ float g_sims[(size_t)T_DIM * V_DIM * L_DIM * F_DIM];
// Compaction list of pairs with >=2 survivors (heavy path).
__device__ int g_count;
__device__ int g_list[T_DIM * V_DIM];
// Fixup list of flagged (m,n) entries needing exact recompute.
#define CAP_FIX (1 << 22)
__device__ int g_fix_count;
__device__ int g_fix[CAP_FIX];

__global__ void init_counters_kernel() { g_count = 0; g_fix_count = 0; }

// TF32 input quantization (cvt.rna: round-to-nearest, 11-bit mantissa)
__device__ __forceinline__ float to_tf32(float x) {
    unsigned int u;
    asm("cvt.rna.tf32.f32 %0, %1;" : "=r"(u) : "f"(x));
    return __uint_as_float(u);
}

// ---------------------------------------------------------------------------
// Kernel 1: TF32 tensor-core screening GEMM.
// M=8192 (t*32+l), N=3072 (v*12+f), K=512. CTA 128x128, BK=32, 8 warps,
// warp tile 64x32 (4 m-tiles x 4 n-tiles of m16n8k8). Writes approx sims;
// flags entries > FLAG_THR into g_fix for exact recompute.
// ---------------------------------------------------------------------------
__global__ void __launch_bounds__(256, 2) sims_mma_kernel(
    const float* __restrict__ A,   // text_embeds  [8192, 512]
    const float* __restrict__ B)   // video_embeds [3072, 512]
{
    __shared__ float As[128][36];   // stride 36: conflict-free frag loads
    __shared__ float Bs[128][36];

    const int tid  = threadIdx.x;
    const int bm   = blockIdx.y;
    const int bn   = blockIdx.x;
    const int warp = tid >> 5;
    const int lane = tid & 31;
    const int grp  = lane >> 2;     // 0..7
    const int qid  = lane & 3;      // 0..3
    const int wm   = (warp & 1) * 64;    // warp m-offset within CTA tile
    const int wn   = (warp >> 1) * 32;   // warp n-offset

    const float* Ab = A + (size_t)bm * 128 * D_DIM;
    const float* Bb = B + (size_t)bn * 128 * D_DIM;

    float acc[4][4][4];
#pragma unroll
    for (int mt = 0; mt < 4; mt++)
#pragma unroll
        for (int nt = 0; nt < 4; nt++)
#pragma unroll
            for (int e = 0; e < 4; e++) acc[mt][nt][e] = 0.0f;

#pragma unroll 1
    for (int kt = 0; kt < D_DIM / 32; kt++) {
        __syncthreads();   // previous iteration's frag reads done
#pragma unroll
        for (int i = 0; i < 4; i++) {
            const int f4  = tid + i * 256;      // 0..1023
            const int row = f4 >> 3;
            const int c4  = (f4 & 7) << 2;
            float4 va = *(const float4*)(Ab + (size_t)row * D_DIM + kt * 32 + c4);
            As[row][c4 + 0] = to_tf32(va.x);
            As[row][c4 + 1] = to_tf32(va.y);
            As[row][c4 + 2] = to_tf32(va.z);
            As[row][c4 + 3] = to_tf32(va.w);
            float4 vb = *(const float4*)(Bb + (size_t)row * D_DIM + kt * 32 + c4);
            Bs[row][c4 + 0] = to_tf32(vb.x);
            Bs[row][c4 + 1] = to_tf32(vb.y);
            Bs[row][c4 + 2] = to_tf32(vb.z);
            Bs[row][c4 + 3] = to_tf32(vb.w);
        }
        __syncthreads();

#pragma unroll
        for (int k0 = 0; k0 < 32; k0 += 8) {
            unsigned int af[4][4], bf[4][2];
#pragma unroll
            for (int mt = 0; mt < 4; mt++) {
                const int r = wm + mt * 16 + grp;
                af[mt][0] = __float_as_uint(As[r][k0 + qid]);
                af[mt][1] = __float_as_uint(As[r + 8][k0 + qid]);
                af[mt][2] = __float_as_uint(As[r][k0 + qid + 4]);
                af[mt][3] = __float_as_uint(As[r + 8][k0 + qid + 4]);
            }
#pragma unroll
            for (int nt = 0; nt < 4; nt++) {
                const int cb = wn + nt * 8 + grp;
                bf[nt][0] = __float_as_uint(Bs[cb][k0 + qid]);
                bf[nt][1] = __float_as_uint(Bs[cb][k0 + qid + 4]);
            }
#pragma unroll
            for (int mt = 0; mt < 4; mt++)
#pragma unroll
                for (int nt = 0; nt < 4; nt++) {
                    asm volatile(
                        "mma.sync.aligned.m16n8k8.row.col.f32.tf32.tf32.f32 "
                        "{%0,%1,%2,%3}, {%4,%5,%6,%7}, {%8,%9}, {%0,%1,%2,%3};\n"
                        : "+f"(acc[mt][nt][0]), "+f"(acc[mt][nt][1]),
                          "+f"(acc[mt][nt][2]), "+f"(acc[mt][nt][3])
                        : "r"(af[mt][0]), "r"(af[mt][1]),
                          "r"(af[mt][2]), "r"(af[mt][3]),
                          "r"(bf[nt][0]), "r"(bf[nt][1]));
                }
        }
    }

    // Epilogue: scatter approx values; flag candidates for exact recompute.
    // c0:(grp,2q) c1:(grp,2q+1) c2:(grp+8,2q) c3:(grp+8,2q+1)
#pragma unroll
    for (int mt = 0; mt < 4; mt++)
#pragma unroll
        for (int nt = 0; nt < 4; nt++)
#pragma unroll
            for (int e = 0; e < 4; e++) {
                const int m = bm * 128 + wm + mt * 16 + grp + ((e & 2) ? 8 : 0);
                const int n = bn * 128 + wn + nt * 8 + 2 * qid + (e & 1);
                const float val = acc[mt][nt][e];
                const int tt = m >> 5, ll = m & 31;
                const int vv = n / 12,  ff = n - vv * 12;
                g_sims[(size_t)((tt << 8) + vv) * (L_DIM * F_DIM) + ll * F_DIM + ff] = val;
                if (val > FLAG_THR) {
                    const int slot = atomicAdd(&g_fix_count, 1);
                    if (slot < CAP_FIX) g_fix[slot] = m * 3072 + n;
                }
            }
}

// ---------------------------------------------------------------------------
// Kernel 1b: exact recompute of flagged entries. Sequential-k fmaf chain ==
// the R13-R15 GEMM's per-element order: BIT-IDENTICAL survivor values.
// ---------------------------------------------------------------------------
__global__ void __launch_bounds__(256) fixup_kernel(
    const float* __restrict__ A,
    const float* __restrict__ B)
{
    const int count = min(g_fix_count, CAP_FIX);
    const int stride = gridDim.x * blockDim.x;
#pragma unroll 1
    for (int i = blockIdx.x * blockDim.x + threadIdx.x; i < count; i += stride) {
        const int e = g_fix[i];
        const int m = e / 3072;
        const int n = e - m * 3072;
        const float4* a4 = (const float4*)(A + (size_t)m * D_DIM);
        const float4* b4 = (const float4*)(B + (size_t)n * D_DIM);
        float acc = 0.0f;
#pragma unroll 8
        for (int d = 0; d < D_DIM / 4; d++) {
            const float4 a = __ldg(a4 + d);
            const float4 b = __ldg(b4 + d);
            acc = fmaf(a.x, b.x, acc);
            acc = fmaf(a.y, b.y, acc);
            acc = fmaf(a.z, b.z, acc);
            acc = fmaf(a.w, b.w, acc);
        }
        const int tt = m >> 5, ll = m & 31;
        const int vv = n / 12,  ff = n - vv * 12;
        g_sims[(size_t)((tt << 8) + vv) * (L_DIM * F_DIM) + ll * F_DIM + ff] = acc;
    }
}

// XLA:GPU exp: accurate expf, output FTZ (results < FLT_MIN -> exact 0).
__device__ __forceinline__ float ref_exp(float arg) {
    const float w = expf(arg);
    return (w < FLT_MIN_NORMAL) ? 0.0f : w;
}

// w for entry s. Skips expf when provably flushed (s <= S_SKIP).
__device__ __forceinline__ float entry_w(float s) {
    if (s <= S_SKIP) return 0.0f;
    return ref_exp(__fdiv_rn(s - 1.0f, 0.01f));
}

// ---------------------------------------------------------------------------
// Kernel 2a (prep): classify pairs. k==0 -> 0. k==1 -> scalar recurrence with
// exact period-2 cycle shortcut. k>=2 -> compact list.
// ---------------------------------------------------------------------------
__global__ void __launch_bounds__(256) sinkhorn_prep_kernel(
    const float* __restrict__ cap_mask,   // [256, 32]
    const float* __restrict__ vid_mask,   // [256, 12]
    float* __restrict__ out)              // [256, 256]
{
    const unsigned FULL = 0xffffffffu;
    const int gtid = blockIdx.x * blockDim.x + threadIdx.x;
    const int warp = gtid >> 5;
    const int lane = threadIdx.x & 31;
    const int g    = lane & 7;
    const int pair = warp * 4 + (lane >> 3);
    const int t    = pair >> 8;
    const int v    = pair & 255;

    const float4* sp = (const float4*)(g_sims + (size_t)pair * (L_DIM * F_DIM));

    float capv[4];
#pragma unroll
    for (int j = 0; j < 4; j++) capv[j] = cap_mask[t * L_DIM + g + 8 * j];
    float vm[12];
    {
        const float4* vmp = (const float4*)(vid_mask + v * F_DIM);
        float4 m0 = vmp[0], m1 = vmp[1], m2 = vmp[2];
        vm[0] = m0.x; vm[1] = m0.y; vm[2]  = m0.z; vm[3]  = m0.w;
        vm[4] = m1.x; vm[5] = m1.y; vm[6]  = m1.z; vm[7]  = m1.w;
        vm[8] = m2.x; vm[9] = m2.y; vm[10] = m2.z; vm[11] = m2.w;
    }

    float nCap = 0.0f;
#pragma unroll
    for (int j = 0; j < 4; j++) nCap += (capv[j] != 0.0f) ? 1.0f : 0.0f;
#pragma unroll
    for (int m = 1; m < 8; m <<= 1) nCap += __shfl_xor_sync(FULL, nCap, m);
    float nVid = 0.0f;
#pragma unroll
    for (int f = 0; f < 12; f++) nVid += (vm[f] != 0.0f) ? 1.0f : 0.0f;
    const bool capAny = nCap > 0.0f;
    const bool vidAny = nVid > 0.0f;

    int   cnt = 0;
    float w1 = 0.0f, r1 = 0.0f, c1 = 0.0f, s1 = 0.0f;
#pragma unroll
    for (int j = 0; j < 4; j++) {
        const int row = g + 8 * j;
        const float rj = (capv[j] != 0.0f && vidAny) ? (1.0f / nCap) : 0.0f;
        float4 x0 = sp[row * 3 + 0];
        float4 x1 = sp[row * 3 + 1];
        float4 x2 = sp[row * 3 + 2];
        float s[12];
        s[0] = x0.x; s[1] = x0.y; s[2]  = x0.z; s[3]  = x0.w;
        s[4] = x1.x; s[5] = x1.y; s[6]  = x1.z; s[7]  = x1.w;
        s[8] = x2.x; s[9] = x2.y; s[10] = x2.z; s[11] = x2.w;
#pragma unroll
        for (int f = 0; f < 12; f++) {
            float w = entry_w(s[f]);
            w = (capv[j] != 0.0f && vm[f] != 0.0f) ? w : 0.0f;
            if (w != 0.0f) {
                cnt++;
                w1 = w;
                r1 = rj;
                c1 = (vm[f] != 0.0f && capAny) ? (1.0f / nVid) : 0.0f;
                s1 = s[f];
            }
        }
    }
    int k = cnt;
#pragma unroll
    for (int m = 1; m < 8; m <<= 1) k += __shfl_xor_sync(FULL, k, m);

    if (k == 0) {
        if (g == 0) out[pair] = 0.0f;
    } else if (k == 1) {
        float xa = w1 * __fdividef(1.0f, w1 + SINK_EPS);   // x_0
        float xb;
        {
            float tmp = xa * __fdividef(r1, SINK_EPS + xa);
            xb = tmp * __fdividef(c1, tmp + SINK_EPS);     // x_1
        }
        float xf = xb;
#pragma unroll 1
        for (int i = 2; i <= SINK_ITERS; i++) {
            float tmp = xb * __fdividef(r1, SINK_EPS + xb);
            float xc = tmp * __fdividef(c1, tmp + SINK_EPS);   // x_i
            if (__float_as_uint(xc) == __float_as_uint(xa)) {
                xf = (((SINK_ITERS - i) & 1) == 0) ? xc : xb;
                break;
            }
            xa = xb; xb = xc; xf = xc;
        }
        if (cnt == 1) out[pair] = fmaf(s1, xf, 0.0f);
    }

    const bool isLive = (k >= 2) && (g == 0);
    const unsigned bal = __ballot_sync(FULL, isLive);
    if (bal) {
        const int leader = __ffs(bal) - 1;
        int base = 0;
        if (lane == leader) base = atomicAdd(&g_count, __popc(bal));
        base = __shfl_sync(FULL, base, leader);
        if (isLive)
            g_list[base + __popc(bal & ((1u << lane) - 1))] = pair;
    }
}

// ---------------------------------------------------------------------------
// Kernel 2b (heavy): literal dense Sinkhorn over the k>=2 list (bit-exact
// R13 arithmetic). Idle warps exit; duplicates benign.
// ---------------------------------------------------------------------------
__global__ void __launch_bounds__(256, 2) sinkhorn_heavy_kernel(
    const float* __restrict__ cap_mask,
    const float* __restrict__ vid_mask,
    float* __restrict__ out)
{
    const unsigned FULL = 0xffffffffu;
    const int gtid = blockIdx.x * blockDim.x + threadIdx.x;
    const int warp = gtid >> 5;
    const int lane = threadIdx.x & 31;
    const int g    = lane & 7;

    const int count = g_count;
    if (warp * 4 >= count) return;
    int lidx = warp * 4 + (lane >> 3);
    if (lidx >= count) lidx = count - 1;
    const int pair = g_list[lidx];
    const int t    = pair >> 8;
    const int v    = pair & 255;

    const float4* sp = (const float4*)(g_sims + (size_t)pair * (L_DIM * F_DIM));

    float capv[4];
#pragma unroll
    for (int j = 0; j < 4; j++) capv[j] = cap_mask[t * L_DIM + g + 8 * j];
    float vm[12];
    {
        const float4* vmp = (const float4*)(vid_mask + v * F_DIM);
        float4 m0 = vmp[0], m1 = vmp[1], m2 = vmp[2];
        vm[0] = m0.x; vm[1] = m0.y; vm[2]  = m0.z; vm[3]  = m0.w;
        vm[4] = m1.x; vm[5] = m1.y; vm[6]  = m1.z; vm[7]  = m1.w;
        vm[8] = m2.x; vm[9] = m2.y; vm[10] = m2.z; vm[11] = m2.w;
    }

    float nCap = 0.0f;
#pragma unroll
    for (int j = 0; j < 4; j++) nCap += (capv[j] != 0.0f) ? 1.0f : 0.0f;
#pragma unroll
    for (int m = 1; m < 8; m <<= 1) nCap += __shfl_xor_sync(FULL, nCap, m);
    float nVid = 0.0f;
#pragma unroll
    for (int f = 0; f < 12; f++) nVid += (vm[f] != 0.0f) ? 1.0f : 0.0f;
    const bool capAny = nCap > 0.0f;
    const bool vidAny = nVid > 0.0f;

    float r[4];
#pragma unroll
    for (int j = 0; j < 4; j++)
        r[j] = (capv[j] != 0.0f && vidAny) ? (1.0f / nCap) : 0.0f;
    float c[12];
#pragma unroll
    for (int f = 0; f < 12; f++)
        c[f] = (vm[f] != 0.0f && capAny) ? (1.0f / nVid) : 0.0f;

    float P[4][12];
    float S = 0.0f;
#pragma unroll
    for (int j = 0; j < 4; j++) {
        const int row = g + 8 * j;
        float4 x0 = sp[row * 3 + 0];
        float4 x1 = sp[row * 3 + 1];
        float4 x2 = sp[row * 3 + 2];
        float s[12];
        s[0] = x0.x; s[1] = x0.y; s[2]  = x0.z; s[3]  = x0.w;
        s[4] = x1.x; s[5] = x1.y; s[6]  = x1.z; s[7]  = x1.w;
        s[8] = x2.x; s[9] = x2.y; s[10] = x2.z; s[11] = x2.w;
#pragma unroll
        for (int f = 0; f < 12; f++) {
            float w = entry_w(s[f]);
            w = (capv[j] != 0.0f && vm[f] != 0.0f) ? w : 0.0f;
            P[j][f] = w;
            S += w;
        }
    }
#pragma unroll
    for (int m = 1; m < 8; m <<= 1) S += __shfl_xor_sync(FULL, S, m);

    const float s0 = __fdividef(1.0f, S + SINK_EPS);
#pragma unroll
    for (int j = 0; j < 4; j++)
#pragma unroll
        for (int f = 0; f < 12; f++) P[j][f] *= s0;

#pragma unroll 1
    for (int it = 0; it < SINK_ITERS; it++) {
#pragma unroll
        for (int j = 0; j < 4; j++) {
            float u = SINK_EPS;
#pragma unroll
            for (int f = 0; f < 12; f++) u += P[j][f];
            const float q = __fdividef(r[j], u);
#pragma unroll
            for (int f = 0; f < 12; f++) P[j][f] *= q;
        }
        float p[12];
#pragma unroll
        for (int f = 0; f < 12; f++)
            p[f] = (P[0][f] + P[1][f]) + (P[2][f] + P[3][f]);
#pragma unroll
        for (int m = 1; m < 8; m <<= 1)
#pragma unroll
            for (int f = 0; f < 12; f++)
                p[f] += __shfl_xor_sync(FULL, p[f], m);
#pragma unroll
        for (int f = 0; f < 12; f++) {
            const float qc = __fdividef(c[f], p[f] + SINK_EPS);
#pragma unroll
            for (int j = 0; j < 4; j++) P[j][f] *= qc;
        }
    }

    float acc = 0.0f;
#pragma unroll
    for (int j = 0; j < 4; j++) {
        const int row = g + 8 * j;
        float4 x0 = sp[row * 3 + 0];
        float4 x1 = sp[row * 3 + 1];
        float4 x2 = sp[row * 3 + 2];
        float s[12];
        s[0] = x0.x; s[1] = x0.y; s[2]  = x0.z; s[3]  = x0.w;
        s[4] = x1.x; s[5] = x1.y; s[6]  = x1.z; s[7]  = x1.w;
        s[8] = x2.x; s[9] = x2.y; s[10] = x2.z; s[11] = x2.w;
#pragma unroll
        for (int f = 0; f < 12; f++) acc = fmaf(s[f], P[j][f], acc);
    }
#pragma unroll
    for (int m = 1; m < 8; m <<= 1) acc += __shfl_xor_sync(FULL, acc, m);

    if (g == 0) out[pair] = acc;
}

// ---------------------------------------------------------------------------
extern "C" void kernel_launch(void* const* d_in, const int* in_sizes, int n_in,
                              void* d_out, int out_size)
{
    const float* te  = 0;   // 4194304
    const float* ve  = 0;   // 1572864
    const float* cap = 0;   // 8192
    const float* vid = 0;   // 3072
    for (int i = 0; i < n_in; i++) {
        switch (in_sizes[i]) {
            case 4194304: te  = (const float*)d_in[i]; break;
            case 1572864: ve  = (const float*)d_in[i]; break;
            case 8192:    cap = (const float*)d_in[i]; break;
            case 3072:    vid = (const float*)d_in[i]; break;
            default: break;
        }
    }
    if (!te)  te  = (const float*)d_in[0];
    if (!ve)  ve  = (const float*)d_in[1];
    if (!cap) cap = (const float*)d_in[2];
    if (!vid) vid = (const float*)d_in[3];

    float* out = (float*)d_out;                 // [256,256] float32

    init_counters_kernel<<<1, 1>>>();

    dim3 gemm_grid(3072 / 128, 8192 / 128);     // (24, 64)
    sims_mma_kernel<<<gemm_grid, 256>>>(te, ve);

    fixup_kernel<<<512, 256>>>(te, ve);

    sinkhorn_prep_kernel<<<2048, 256>>>(cap, vid, out);
    sinkhorn_heavy_kernel<<<2048, 256>>>(cap, vid, out);
}